// round 12
// baseline (speedup 1.0000x reference)
#include <cuda_runtime.h>
#include <cuda_bf16.h>
#include <cstdint>

// Problem constants
#define NJ 52
#define NB 32
#define MT 128           // vertices per CTA (GEMM M tile)
#define NTG 48           // n-tiles of 8 (total N = 384 permuted cols)
#define THREADS 256      // 8 warps: 4 (M) x 2 (N)
#define NCHUNK 4         // N chunks of 96 cols

// Main-kernel SMEM (dynamic): A hi/lo only
#define S_AHI 0
#define S_ALO (S_AHI + MT * 128)          // 16384
#define S_TOTAL (S_ALO + MT * 128)        // 32768

#define SW128(b) ((b) ^ (((b) >> 3) & 0x70))

// B fragments, hi/lo interleaved: [ntg][kt][lane] -> uint4 {bh0,bh1,bl0,bl1}
// Column permutation: within 48-col group g, position p = 8t+2q+d holds
// (batch 4g+q, element e = 2t+d) of M rows 0..2 flattened (e = i*4+k).
__device__ __align__(16) uint4 g_Bf[NTG * 4 * 32];

__device__ __forceinline__ uint32_t smem_u32(const void* p) {
    uint32_t a;
    asm("{ .reg .u64 t; cvta.to.shared.u64 t, %1; cvt.u32.u64 %0, t; }"
        : "=r"(a) : "l"(p));
    return a;
}

__device__ __forceinline__ void ldsm_x4(uint32_t* d, uint32_t addr) {
    asm volatile("ldmatrix.sync.aligned.m8n8.x4.shared.b16 {%0,%1,%2,%3}, [%4];"
                 : "=r"(d[0]), "=r"(d[1]), "=r"(d[2]), "=r"(d[3]) : "r"(addr));
}

__device__ __forceinline__ void ldsm_x2(uint32_t& d0, uint32_t& d1, uint32_t addr) {
    asm volatile("ldmatrix.sync.aligned.m8n8.x2.shared.b16 {%0,%1}, [%2];"
                 : "=r"(d0), "=r"(d1) : "r"(addr));
}

__device__ __forceinline__ void mma_bf16(float* c, const uint32_t* a,
                                         uint32_t b0, uint32_t b1) {
    asm volatile(
        "mma.sync.aligned.m16n8k16.row.col.f32.bf16.bf16.f32 "
        "{%0,%1,%2,%3}, {%4,%5,%6,%7}, {%8,%9}, {%0,%1,%2,%3};"
        : "+f"(c[0]), "+f"(c[1]), "+f"(c[2]), "+f"(c[3])
        : "r"(a[0]), "r"(a[1]), "r"(a[2]), "r"(a[3]), "r"(b0), "r"(b1));
}

__device__ __forceinline__ void split_bf16(float x, __nv_bfloat16& hi, __nv_bfloat16& lo) {
    hi = __float2bfloat16(x);
    lo = __float2bfloat16(x - __bfloat162float(hi));
}

// ---------------- Prep kernel: build permuted B fragments (48 CTAs) ---------
__global__ void __launch_bounds__(THREADS)
prep_B_kernel(const float* __restrict__ M) {
    __shared__ __align__(128) char pb[2 * 8 * 128];   // [hi|lo] 8 rows x 128B
    const int tid = threadIdx.x;
    const int lane = tid & 31;
    const int ntg = blockIdx.x;

    if (tid < 8 * 32) {                 // one (row, col-pair) per thread
        const int nl = tid >> 5;        // local n row 0..7 = 2q+d
        const int jp = tid & 31;
        // Permuted mapping: group g = ntg/6, tile t = ntg%6
        const int g = ntg / 6;
        const int t = ntg - g * 6;
        const int b = 4 * g + (nl >> 1);   // batch
        const int e = 2 * t + (nl & 1);    // element 0..11 (rows 0..2 of 4x4)
        const int j0 = 2 * jp, j1 = 2 * jp + 1;
        float m0 = (j0 < NJ) ? M[((size_t)b * NJ + j0) * 16 + e] : 0.0f;
        float m1 = (j1 < NJ) ? M[((size_t)b * NJ + j1) * 16 + e] : 0.0f;
        __nv_bfloat16 h0, l0, h1, l1;
        split_bf16(m0, h0, l0);
        split_bf16(m1, h1, l1);
        uint32_t off = SW128((uint32_t)(nl * 128 + jp * 4));
        __nv_bfloat162 hp; hp.x = h0; hp.y = h1;
        __nv_bfloat162 lp; lp.x = l0; lp.y = l1;
        *reinterpret_cast<__nv_bfloat162*>(pb + off) = hp;
        *reinterpret_cast<__nv_bfloat162*>(pb + 1024 + off) = lp;
    }
    __syncthreads();

    if (tid < 32) {
        const uint32_t sbp = smem_u32(pb);
        const int bsub = (lane >> 3) & 1;
        const int brin = lane & 7;
        #pragma unroll
        for (int kt = 0; kt < 4; kt++) {
            const uint32_t byte = (uint32_t)(brin * 128 + kt * 32 + bsub * 16);
            const uint32_t sw = SW128(byte);
            uint32_t h0, h1, l0, l1;
            ldsm_x2(h0, h1, sbp + sw);
            ldsm_x2(l0, l1, sbp + 1024 + sw);
            g_Bf[(ntg * 4 + kt) * 32 + lane] = make_uint4(h0, h1, l0, l1);
        }
    }
}

// ---------------- Main kernel ----------------------------------------------
__global__ void __launch_bounds__(THREADS, 2)
skin_mma_kernel(const float* __restrict__ verts,   // [V,3]
                const float* __restrict__ W,       // [V,NJ]
                float* __restrict__ out,           // [NB,V,3]
                int V) {
    extern __shared__ char smem[];
    const uint32_t sb = smem_u32(smem);
    const int tid = threadIdx.x;
    const int lane = tid & 31;
    const int wid = tid >> 5;
    const int warp_m = wid >> 1;     // 0..3
    const int warp_n = wid & 1;      // 0..1
    const int vbase = blockIdx.x * MT;

    // ---- Zero only the K-pad bytes 104..127 of each A row (hi & lo) ----
    {
        const uint2 z = make_uint2(0, 0);
        for (int i = tid; i < MT * 3 * 2; i += THREADS) {  // 768 uint2
            const int arr = (i >= MT * 3);
            const int k = arr ? (i - MT * 3) : i;
            const int r = k / 3;
            const int q = k - r * 3;
            const uint32_t off = SW128((uint32_t)(r * 128 + 104 + q * 8));
            *reinterpret_cast<uint2*>(smem + (arr ? S_ALO : S_AHI) + off) = z;
        }
    }

    // ---- Coalesced A fill: W block contiguous 128*52 floats = 1664 uint4 ----
    {
        const uint4* wp4 = reinterpret_cast<const uint4*>(W + (size_t)vbase * NJ);
        const int lim4 = (V - vbase) * (NJ / 4);   // valid uint4 count in block
        for (int i = tid; i < MT * (NJ / 4); i += THREADS) {
            uint4 raw = (i < lim4) ? wp4[i] : make_uint4(0, 0, 0, 0);
            const int r = i / (NJ / 4);
            const int q = i - r * (NJ / 4);
            const float* f = reinterpret_cast<const float*>(&raw);
            __nv_bfloat16 h[4], l[4];
            #pragma unroll
            for (int u = 0; u < 4; u++) split_bf16(f[u], h[u], l[u]);
            uint32_t hp0, hp1, lp0, lp1;
            {
                __nv_bfloat162 t;
                t.x = h[0]; t.y = h[1]; hp0 = *reinterpret_cast<uint32_t*>(&t);
                t.x = h[2]; t.y = h[3]; hp1 = *reinterpret_cast<uint32_t*>(&t);
                t.x = l[0]; t.y = l[1]; lp0 = *reinterpret_cast<uint32_t*>(&t);
                t.x = l[2]; t.y = l[3]; lp1 = *reinterpret_cast<uint32_t*>(&t);
            }
            const uint32_t off = SW128((uint32_t)(r * 128 + q * 8));  // 8B-aligned
            *reinterpret_cast<uint2*>(smem + S_AHI + off) = make_uint2(hp0, hp1);
            *reinterpret_cast<uint2*>(smem + S_ALO + off) = make_uint2(lp0, lp1);
        }
    }
    __syncthreads();   // the ONLY block-wide sync

    // ---- A-hi fragments persistent; A-lo reloaded per kt via base addr ----
    uint32_t ah[2][4][4];
    uint32_t aBaseLo[2];
    {
        const int sub = lane >> 3;
        const int rin = lane & 7;
        #pragma unroll
        for (int mt = 0; mt < 2; mt++) {
            const int row = warp_m * 32 + mt * 16 + rin + (sub & 1) * 8;
            const uint32_t byte = (uint32_t)(row * 128 + (sub >> 1) * 16);
            const uint32_t sw = SW128(byte);   // byte bits 5-6 are 0 -> kt via XOR
            const uint32_t baseHi = sb + S_AHI + sw;
            aBaseLo[mt] = sb + S_ALO + sw;
            #pragma unroll
            for (int kt = 0; kt < 4; kt++)
                ldsm_x4(ah[mt][kt], baseHi ^ (uint32_t)(kt * 32));
        }
    }

    // ---- Per-lane vertex coords for its 4 output rows (reused all chunks) ---
    // rows: warp_m*32 + mt*16 + half*8 + (lane>>2)
    float vx[4], vy[4], vz[4];
    int   vrow[4];
    {
        const int rg = lane >> 2;
        #pragma unroll
        for (int rr = 0; rr < 4; rr++) {
            const int mt = rr >> 1, half = rr & 1;
            const int row = warp_m * 32 + mt * 16 + half * 8 + rg;
            const int v = vbase + row;
            const int vc = (v < V) ? v : (V - 1);
            vrow[rr] = row;
            vx[rr] = verts[(size_t)vc * 3 + 0];
            vy[rr] = verts[(size_t)vc * 3 + 1];
            vz[rr] = verts[(size_t)vc * 3 + 2];
        }
    }
    const int q = lane & 3;

    // ---- N chunks: mma -> in-register fold -> store. No syncs. ----
    for (int c = 0; c < NCHUNK; c++) {
        float acc[2][6][4] = {};

        #pragma unroll
        for (int kt = 0; kt < 4; kt++) {
            uint32_t al0[4], al1[4];
            ldsm_x4(al0, aBaseLo[0] ^ (uint32_t)(kt * 32));
            ldsm_x4(al1, aBaseLo[1] ^ (uint32_t)(kt * 32));
            #pragma unroll
            for (int nt = 0; nt < 6; nt++) {
                const int ntg = c * 12 + warp_n * 6 + nt;
                const uint4 b = g_Bf[(ntg * 4 + kt) * 32 + lane];
                mma_bf16(acc[0][nt], ah[0][kt], b.x, b.y);   // hi*hi
                mma_bf16(acc[1][nt], ah[1][kt], b.x, b.y);
                mma_bf16(acc[0][nt], al0, b.x, b.y);         // lo*hi
                mma_bf16(acc[1][nt], al1, b.x, b.y);
                mma_bf16(acc[0][nt], ah[0][kt], b.z, b.w);   // hi*lo
                mma_bf16(acc[1][nt], ah[1][kt], b.z, b.w);
            }
        }

        // ---- In-register fold + store ----
        // Lane's batch this chunk: group g = 2c + warp_n, b = 4g + q.
        const int b = 8 * c + 4 * warp_n + q;
        #pragma unroll
        for (int rr = 0; rr < 4; rr++) {
            const int mt = rr >> 1;
            const int hb = (rr & 1) * 2;   // 0 for rows rg, 2 for rows rg+8
            const float x = vx[rr], y = vy[rr], z = vz[rr];
            // e = 2*nt + d; acc[mt][nt][hb+d]; o_i from e=4i..4i+3
            const float o0 = fmaf(acc[mt][0][hb], x, fmaf(acc[mt][0][hb + 1], y,
                             fmaf(acc[mt][1][hb], z, acc[mt][1][hb + 1])));
            const float o1 = fmaf(acc[mt][2][hb], x, fmaf(acc[mt][2][hb + 1], y,
                             fmaf(acc[mt][3][hb], z, acc[mt][3][hb + 1])));
            const float o2 = fmaf(acc[mt][4][hb], x, fmaf(acc[mt][4][hb + 1], y,
                             fmaf(acc[mt][5][hb], z, acc[mt][5][hb + 1])));
            const int v = vbase + vrow[rr];
            if (v < V) {
                float* op = out + ((size_t)b * V + v) * 3;
                op[0] = o0; op[1] = o1; op[2] = o2;
            }
        }
    }
}

extern "C" void kernel_launch(void* const* d_in, const int* in_sizes, int n_in,
                              void* d_out, int out_size) {
    const float* verts = (const float*)d_in[0];   // [1,V,3]
    const float* W     = (const float*)d_in[1];   // [1,V,NJ]
    const float* M     = (const float*)d_in[2];   // [NB,NJ,4,4]
    float* out         = (float*)d_out;           // [NB,V,3]

    const int V = in_sizes[0] / 3;

    cudaFuncSetAttribute(skin_mma_kernel,
                         cudaFuncAttributeMaxDynamicSharedMemorySize, S_TOTAL);

    prep_B_kernel<<<NTG, THREADS>>>(M);

    const int grid = (V + MT - 1) / MT;
    skin_mma_kernel<<<grid, THREADS, S_TOTAL>>>(verts, W, out, V);
}

// round 13
// speedup vs baseline: 1.3516x; 1.3516x over previous
#include <cuda_runtime.h>
#include <cuda_bf16.h>
#include <cstdint>

// Problem constants
#define NJ 52
#define NB 32
#define MT 128           // vertices per CTA (GEMM M tile)
#define NTG 48           // n-tiles of 8 (total N = 384 permuted cols)
#define THREADS 256      // 8 warps: 4 (M) x 2 (N)
#define NCHUNK 4         // N chunks of 96 cols

// Main-kernel SMEM (dynamic): A hi/lo only
#define S_AHI 0
#define S_ALO (S_AHI + MT * 128)          // 16384
#define S_TOTAL (S_ALO + MT * 128)        // 32768

#define SW128(b) ((b) ^ (((b) >> 3) & 0x70))

// B fragments, hi/lo interleaved: [ntg][kt][lane] -> uint4 {bh0,bh1,bl0,bl1}
// Column permutation: within 48-col group g, position p = 8t+2q+d holds
// (batch 4g+q, element e = 2t+d), e = i*4+k over rows 0..2 of the 4x4.
__device__ __align__(16) uint4 g_Bf[NTG * 4 * 32];

__device__ __forceinline__ uint32_t smem_u32(const void* p) {
    uint32_t a;
    asm("{ .reg .u64 t; cvta.to.shared.u64 t, %1; cvt.u32.u64 %0, t; }"
        : "=r"(a) : "l"(p));
    return a;
}

__device__ __forceinline__ void ldsm_x4(uint32_t* d, uint32_t addr) {
    asm volatile("ldmatrix.sync.aligned.m8n8.x4.shared.b16 {%0,%1,%2,%3}, [%4];"
                 : "=r"(d[0]), "=r"(d[1]), "=r"(d[2]), "=r"(d[3]) : "r"(addr));
}

__device__ __forceinline__ void ldsm_x2(uint32_t& d0, uint32_t& d1, uint32_t addr) {
    asm volatile("ldmatrix.sync.aligned.m8n8.x2.shared.b16 {%0,%1}, [%2];"
                 : "=r"(d0), "=r"(d1) : "r"(addr));
}

__device__ __forceinline__ void mma_bf16(float* c, const uint32_t* a,
                                         uint32_t b0, uint32_t b1) {
    asm volatile(
        "mma.sync.aligned.m16n8k16.row.col.f32.bf16.bf16.f32 "
        "{%0,%1,%2,%3}, {%4,%5,%6,%7}, {%8,%9}, {%0,%1,%2,%3};"
        : "+f"(c[0]), "+f"(c[1]), "+f"(c[2]), "+f"(c[3])
        : "r"(a[0]), "r"(a[1]), "r"(a[2]), "r"(a[3]), "r"(b0), "r"(b1));
}

__device__ __forceinline__ void split_bf16(float x, __nv_bfloat16& hi, __nv_bfloat16& lo) {
    hi = __float2bfloat16(x);
    lo = __float2bfloat16(x - __bfloat162float(hi));
}

// ---------------- Prep kernel: build permuted B fragments (48 CTAs) ---------
__global__ void __launch_bounds__(THREADS)
prep_B_kernel(const float* __restrict__ M) {
    __shared__ __align__(128) char pb[2 * 8 * 128];   // [hi|lo] 8 rows x 128B
    const int tid = threadIdx.x;
    const int lane = tid & 31;
    const int ntg = blockIdx.x;

    if (tid < 8 * 32) {                 // one (row, col-pair) per thread
        const int nl = tid >> 5;        // local n row 0..7 = 2q+d
        const int jp = tid & 31;
        const int g = ntg / 6;
        const int t = ntg - g * 6;
        const int b = 4 * g + (nl >> 1);   // batch
        const int e = 2 * t + (nl & 1);    // element 0..11
        const int j0 = 2 * jp, j1 = 2 * jp + 1;
        float m0 = (j0 < NJ) ? M[((size_t)b * NJ + j0) * 16 + e] : 0.0f;
        float m1 = (j1 < NJ) ? M[((size_t)b * NJ + j1) * 16 + e] : 0.0f;
        __nv_bfloat16 h0, l0, h1, l1;
        split_bf16(m0, h0, l0);
        split_bf16(m1, h1, l1);
        uint32_t off = SW128((uint32_t)(nl * 128 + jp * 4));
        __nv_bfloat162 hp; hp.x = h0; hp.y = h1;
        __nv_bfloat162 lp; lp.x = l0; lp.y = l1;
        *reinterpret_cast<__nv_bfloat162*>(pb + off) = hp;
        *reinterpret_cast<__nv_bfloat162*>(pb + 1024 + off) = lp;
    }
    __syncthreads();

    if (tid < 32) {
        const uint32_t sbp = smem_u32(pb);
        const int bsub = (lane >> 3) & 1;
        const int brin = lane & 7;
        #pragma unroll
        for (int kt = 0; kt < 4; kt++) {
            const uint32_t byte = (uint32_t)(brin * 128 + kt * 32 + bsub * 16);
            const uint32_t sw = SW128(byte);
            uint32_t h0, h1, l0, l1;
            ldsm_x2(h0, h1, sbp + sw);
            ldsm_x2(l0, l1, sbp + 1024 + sw);
            g_Bf[(ntg * 4 + kt) * 32 + lane] = make_uint4(h0, h1, l0, l1);
        }
    }
}

// ---------------- Main kernel ----------------------------------------------
__global__ void __launch_bounds__(THREADS, 2)
skin_mma_kernel(const float* __restrict__ verts,   // [V,3]
                const float* __restrict__ W,       // [V,NJ]
                float* __restrict__ out,           // [NB,V,3]
                int V) {
    extern __shared__ char smem[];
    const uint32_t sb = smem_u32(smem);
    const int tid = threadIdx.x;
    const int lane = tid & 31;
    const int wid = tid >> 5;
    const int warp_m = wid >> 1;     // 0..3
    const int warp_n = wid & 1;      // 0..1
    const int vbase = blockIdx.x * MT;

    // ---- Zero only the K-pad bytes 104..127 of each A row (hi & lo) ----
    {
        const uint2 z = make_uint2(0, 0);
        for (int i = tid; i < MT * 3 * 2; i += THREADS) {  // 768 uint2
            const int arr = (i >= MT * 3);
            const int k = arr ? (i - MT * 3) : i;
            const int r = k / 3;
            const int q = k - r * 3;
            const uint32_t off = SW128((uint32_t)(r * 128 + 104 + q * 8));
            *reinterpret_cast<uint2*>(smem + (arr ? S_ALO : S_AHI) + off) = z;
        }
    }

    // ---- Coalesced A fill: W block contiguous 128*52 floats = 1664 uint4 ----
    {
        const uint4* wp4 = reinterpret_cast<const uint4*>(W + (size_t)vbase * NJ);
        const int lim4 = (V - vbase) * (NJ / 4);   // valid uint4 count in block
        for (int i = tid; i < MT * (NJ / 4); i += THREADS) {
            uint4 raw = (i < lim4) ? wp4[i] : make_uint4(0, 0, 0, 0);
            const int r = i / (NJ / 4);
            const int q = i - r * (NJ / 4);
            const float* f = reinterpret_cast<const float*>(&raw);
            __nv_bfloat16 h[4], l[4];
            #pragma unroll
            for (int u = 0; u < 4; u++) split_bf16(f[u], h[u], l[u]);
            uint32_t hp0, hp1, lp0, lp1;
            {
                __nv_bfloat162 t;
                t.x = h[0]; t.y = h[1]; hp0 = *reinterpret_cast<uint32_t*>(&t);
                t.x = h[2]; t.y = h[3]; hp1 = *reinterpret_cast<uint32_t*>(&t);
                t.x = l[0]; t.y = l[1]; lp0 = *reinterpret_cast<uint32_t*>(&t);
                t.x = l[2]; t.y = l[3]; lp1 = *reinterpret_cast<uint32_t*>(&t);
            }
            const uint32_t off = SW128((uint32_t)(r * 128 + q * 8));  // 8B-aligned
            *reinterpret_cast<uint2*>(smem + S_AHI + off) = make_uint2(hp0, hp1);
            *reinterpret_cast<uint2*>(smem + S_ALO + off) = make_uint2(lp0, lp1);
        }
    }
    __syncthreads();   // the ONLY block-wide sync

    // ---- A fragment base addresses (hi & lo), kt selected via XOR ----
    uint32_t aBaseHi[2], aBaseLo[2];
    {
        const int sub = lane >> 3;
        const int rin = lane & 7;
        #pragma unroll
        for (int mt = 0; mt < 2; mt++) {
            const int row = warp_m * 32 + mt * 16 + rin + (sub & 1) * 8;
            const uint32_t byte = (uint32_t)(row * 128 + (sub >> 1) * 16);
            const uint32_t sw = SW128(byte);   // byte bits 5-6 are 0 -> kt via XOR
            aBaseHi[mt] = sb + S_AHI + sw;
            aBaseLo[mt] = sb + S_ALO + sw;
        }
    }
    const int q = lane & 3;
    const int rg = lane >> 2;

    // ---- N chunks: pipelined B loads, mma, in-register fold. No syncs. ----
    #pragma unroll 1
    for (int c = 0; c < NCHUNK; c++) {
        const uint4* bp = g_Bf + ((size_t)(c * 12 + warp_n * 6) * 4) * 32 + lane;
        float acc[2][6][4] = {};

        uint4 bb[6];
        #pragma unroll
        for (int nt = 0; nt < 6; nt++) bb[nt] = bp[nt * 128];   // kt=0

        #pragma unroll
        for (int kt = 0; kt < 4; kt++) {
            uint32_t ah0[4], ah1[4], al0[4], al1[4];
            ldsm_x4(ah0, aBaseHi[0] ^ (uint32_t)(kt * 32));
            ldsm_x4(ah1, aBaseHi[1] ^ (uint32_t)(kt * 32));
            ldsm_x4(al0, aBaseLo[0] ^ (uint32_t)(kt * 32));
            ldsm_x4(al1, aBaseLo[1] ^ (uint32_t)(kt * 32));

            uint4 bn[6];
            if (kt < 3) {
                #pragma unroll
                for (int nt = 0; nt < 6; nt++) bn[nt] = bp[nt * 128 + (kt + 1) * 32];
            }

            #pragma unroll
            for (int nt = 0; nt < 6; nt++) {
                mma_bf16(acc[0][nt], ah0, bb[nt].x, bb[nt].y);   // hi*hi
                mma_bf16(acc[1][nt], ah1, bb[nt].x, bb[nt].y);
                mma_bf16(acc[0][nt], al0, bb[nt].x, bb[nt].y);   // lo*hi
                mma_bf16(acc[1][nt], al1, bb[nt].x, bb[nt].y);
                mma_bf16(acc[0][nt], ah0, bb[nt].z, bb[nt].w);   // hi*lo
                mma_bf16(acc[1][nt], ah1, bb[nt].z, bb[nt].w);
            }

            if (kt < 3) {
                #pragma unroll
                for (int nt = 0; nt < 6; nt++) bb[nt] = bn[nt];
            }
        }

        // ---- In-register fold + store (coords loaded here; L1-hot) ----
        const int b = 8 * c + 4 * warp_n + q;
        #pragma unroll
        for (int rr = 0; rr < 4; rr++) {
            const int mt = rr >> 1;
            const int hb = (rr & 1) * 2;
            const int row = warp_m * 32 + mt * 16 + (rr & 1) * 8 + rg;
            const int v = vbase + row;
            if (v < V) {
                const float x = verts[(size_t)v * 3 + 0];
                const float y = verts[(size_t)v * 3 + 1];
                const float z = verts[(size_t)v * 3 + 2];
                const float o0 = fmaf(acc[mt][0][hb], x, fmaf(acc[mt][0][hb + 1], y,
                                 fmaf(acc[mt][1][hb], z, acc[mt][1][hb + 1])));
                const float o1 = fmaf(acc[mt][2][hb], x, fmaf(acc[mt][2][hb + 1], y,
                                 fmaf(acc[mt][3][hb], z, acc[mt][3][hb + 1])));
                const float o2 = fmaf(acc[mt][4][hb], x, fmaf(acc[mt][4][hb + 1], y,
                                 fmaf(acc[mt][5][hb], z, acc[mt][5][hb + 1])));
                float* op = out + ((size_t)b * V + v) * 3;
                op[0] = o0; op[1] = o1; op[2] = o2;
            }
        }
    }
}

extern "C" void kernel_launch(void* const* d_in, const int* in_sizes, int n_in,
                              void* d_out, int out_size) {
    const float* verts = (const float*)d_in[0];   // [1,V,3]
    const float* W     = (const float*)d_in[1];   // [1,V,NJ]
    const float* M     = (const float*)d_in[2];   // [NB,NJ,4,4]
    float* out         = (float*)d_out;           // [NB,V,3]

    const int V = in_sizes[0] / 3;

    cudaFuncSetAttribute(skin_mma_kernel,
                         cudaFuncAttributeMaxDynamicSharedMemorySize, S_TOTAL);

    prep_B_kernel<<<NTG, THREADS>>>(M);

    const int grid = (V + MT - 1) / MT;
    skin_mma_kernel<<<grid, THREADS, S_TOTAL>>>(verts, W, out, V);
}

// round 14
// speedup vs baseline: 2.2364x; 1.6547x over previous
#include <cuda_runtime.h>
#include <cuda_fp16.h>
#include <cstdint>

// Problem constants
#define NJ 52
#define NB 32
#define MT 128           // vertices per CTA (GEMM M tile)
#define NTG 48           // n-tiles of 8 (total N = 384 permuted cols)
#define THREADS 256      // 8 warps: 4 (M) x 2 (N)
#define NCHUNK 4         // N chunks of 96 cols

// Main-kernel SMEM (dynamic): A (fp16) only
#define S_A 0
#define S_TOTAL (MT * 128)                // 16384

#define SW128(b) ((b) ^ (((b) >> 3) & 0x70))

// B fragments (fp16): [ntg][kt][lane] -> uint2 {b0,b1}
// Column permutation: within 48-col group g, position p = 8t+2q+d holds
// (batch 4g+q, element e = 2t+d), e = i*4+k over rows 0..2 of the 4x4.
__device__ __align__(16) uint2 g_Bf[NTG * 4 * 32];

__device__ __forceinline__ uint32_t smem_u32(const void* p) {
    uint32_t a;
    asm("{ .reg .u64 t; cvta.to.shared.u64 t, %1; cvt.u32.u64 %0, t; }"
        : "=r"(a) : "l"(p));
    return a;
}

__device__ __forceinline__ void ldsm_x4(uint32_t* d, uint32_t addr) {
    asm volatile("ldmatrix.sync.aligned.m8n8.x4.shared.b16 {%0,%1,%2,%3}, [%4];"
                 : "=r"(d[0]), "=r"(d[1]), "=r"(d[2]), "=r"(d[3]) : "r"(addr));
}

__device__ __forceinline__ void ldsm_x2(uint32_t& d0, uint32_t& d1, uint32_t addr) {
    asm volatile("ldmatrix.sync.aligned.m8n8.x2.shared.b16 {%0,%1}, [%2];"
                 : "=r"(d0), "=r"(d1) : "r"(addr));
}

__device__ __forceinline__ void mma_f16(float* c, const uint32_t* a,
                                        uint32_t b0, uint32_t b1) {
    asm volatile(
        "mma.sync.aligned.m16n8k16.row.col.f32.f16.f16.f32 "
        "{%0,%1,%2,%3}, {%4,%5,%6,%7}, {%8,%9}, {%0,%1,%2,%3};"
        : "+f"(c[0]), "+f"(c[1]), "+f"(c[2]), "+f"(c[3])
        : "r"(a[0]), "r"(a[1]), "r"(a[2]), "r"(a[3]), "r"(b0), "r"(b1));
}

// ---------------- Prep kernel: build permuted B fragments (48 CTAs) ---------
__global__ void __launch_bounds__(THREADS)
prep_B_kernel(const float* __restrict__ M) {
    __shared__ __align__(128) char pb[8 * 128];   // 8 rows x 128B (fp16 K=64)
    const int tid = threadIdx.x;
    const int lane = tid & 31;
    const int ntg = blockIdx.x;

    if (tid < 8 * 32) {                 // one (row, col-pair) per thread
        const int nl = tid >> 5;        // local n row 0..7 = 2q+d
        const int jp = tid & 31;
        const int g = ntg / 6;
        const int t = ntg - g * 6;
        const int b = 4 * g + (nl >> 1);   // batch
        const int e = 2 * t + (nl & 1);    // element 0..11
        const int j0 = 2 * jp, j1 = 2 * jp + 1;
        float m0 = (j0 < NJ) ? M[((size_t)b * NJ + j0) * 16 + e] : 0.0f;
        float m1 = (j1 < NJ) ? M[((size_t)b * NJ + j1) * 16 + e] : 0.0f;
        __half2 hp;
        hp.x = __float2half(m0);
        hp.y = __float2half(m1);
        uint32_t off = SW128((uint32_t)(nl * 128 + jp * 4));
        *reinterpret_cast<__half2*>(pb + off) = hp;
    }
    __syncthreads();

    if (tid < 32) {
        const uint32_t sbp = smem_u32(pb);
        const int bsub = (lane >> 3) & 1;
        const int brin = lane & 7;
        #pragma unroll
        for (int kt = 0; kt < 4; kt++) {
            const uint32_t byte = (uint32_t)(brin * 128 + kt * 32 + bsub * 16);
            const uint32_t sw = SW128(byte);
            uint32_t b0, b1;
            ldsm_x2(b0, b1, sbp + sw);
            g_Bf[(ntg * 4 + kt) * 32 + lane] = make_uint2(b0, b1);
        }
    }
}

// ---------------- Main kernel ----------------------------------------------
__global__ void __launch_bounds__(THREADS, 2)
skin_mma_kernel(const float* __restrict__ verts,   // [V,3]
                const float* __restrict__ W,       // [V,NJ]
                float* __restrict__ out,           // [NB,V,3]
                int V) {
    extern __shared__ char smem[];
    const uint32_t sb = smem_u32(smem);
    const int tid = threadIdx.x;
    const int lane = tid & 31;
    const int wid = tid >> 5;
    const int warp_m = wid >> 1;     // 0..3
    const int warp_n = wid & 1;      // 0..1
    const int vbase = blockIdx.x * MT;

    // ---- Zero only the K-pad bytes 104..127 of each A row ----
    {
        const uint2 z = make_uint2(0, 0);
        for (int i = tid; i < MT * 3; i += THREADS) {   // 384 uint2
            const int r = i / 3;
            const int q = i - r * 3;
            const uint32_t off = SW128((uint32_t)(r * 128 + 104 + q * 8));
            *reinterpret_cast<uint2*>(smem + S_A + off) = z;
        }
    }

    // ---- Coalesced A fill: W block contiguous 128*52 floats = 1664 uint4 ----
    {
        const uint4* wp4 = reinterpret_cast<const uint4*>(W + (size_t)vbase * NJ);
        const int lim4 = (V - vbase) * (NJ / 4);   // valid uint4 count in block
        for (int i = tid; i < MT * (NJ / 4); i += THREADS) {
            uint4 raw = (i < lim4) ? wp4[i] : make_uint4(0, 0, 0, 0);
            const int r = i / (NJ / 4);
            const int q = i - r * (NJ / 4);
            const float* f = reinterpret_cast<const float*>(&raw);
            __half2 p0, p1;
            p0.x = __float2half(f[0]); p0.y = __float2half(f[1]);
            p1.x = __float2half(f[2]); p1.y = __float2half(f[3]);
            uint2 packed;
            packed.x = *reinterpret_cast<uint32_t*>(&p0);
            packed.y = *reinterpret_cast<uint32_t*>(&p1);
            const uint32_t off = SW128((uint32_t)(r * 128 + q * 8));  // 8B-aligned
            *reinterpret_cast<uint2*>(smem + S_A + off) = packed;
        }
    }
    __syncthreads();   // the ONLY block-wide sync

    // ---- A fragments persistent: 2 m-tiles x 4 k-tiles ----
    uint32_t ah[2][4][4];
    {
        const int sub = lane >> 3;
        const int rin = lane & 7;
        #pragma unroll
        for (int mt = 0; mt < 2; mt++) {
            const int row = warp_m * 32 + mt * 16 + rin + (sub & 1) * 8;
            const uint32_t byte = (uint32_t)(row * 128 + (sub >> 1) * 16);
            const uint32_t sw = SW128(byte);   // byte bits 5-6 are 0 -> kt via XOR
            const uint32_t base = sb + S_A + sw;
            #pragma unroll
            for (int kt = 0; kt < 4; kt++)
                ldsm_x4(ah[mt][kt], base ^ (uint32_t)(kt * 32));
        }
    }
    const int q = lane & 3;
    const int rg = lane >> 2;

    // ---- N chunks: pipelined B loads, mma, in-register fold. No syncs. ----
    #pragma unroll 1
    for (int c = 0; c < NCHUNK; c++) {
        const uint2* bp = g_Bf + ((size_t)(c * 12 + warp_n * 6) * 4) * 32 + lane;
        float acc[2][6][4] = {};

        uint2 bb[6];
        #pragma unroll
        for (int nt = 0; nt < 6; nt++) bb[nt] = bp[nt * 128];   // kt=0

        #pragma unroll
        for (int kt = 0; kt < 4; kt++) {
            uint2 bn[6];
            if (kt < 3) {
                #pragma unroll
                for (int nt = 0; nt < 6; nt++) bn[nt] = bp[nt * 128 + (kt + 1) * 32];
            }

            #pragma unroll
            for (int nt = 0; nt < 6; nt++) {
                mma_f16(acc[0][nt], ah[0][kt], bb[nt].x, bb[nt].y);
                mma_f16(acc[1][nt], ah[1][kt], bb[nt].x, bb[nt].y);
            }

            if (kt < 3) {
                #pragma unroll
                for (int nt = 0; nt < 6; nt++) bb[nt] = bn[nt];
            }
        }

        // ---- In-register fold + store ----
        const int b = 8 * c + 4 * warp_n + q;
        #pragma unroll
        for (int rr = 0; rr < 4; rr++) {
            const int mt = rr >> 1;
            const int hb = (rr & 1) * 2;
            const int row = warp_m * 32 + mt * 16 + (rr & 1) * 8 + rg;
            const int v = vbase + row;
            if (v < V) {
                const float x = verts[(size_t)v * 3 + 0];
                const float y = verts[(size_t)v * 3 + 1];
                const float z = verts[(size_t)v * 3 + 2];
                const float o0 = fmaf(acc[mt][0][hb], x, fmaf(acc[mt][0][hb + 1], y,
                                 fmaf(acc[mt][1][hb], z, acc[mt][1][hb + 1])));
                const float o1 = fmaf(acc[mt][2][hb], x, fmaf(acc[mt][2][hb + 1], y,
                                 fmaf(acc[mt][3][hb], z, acc[mt][3][hb + 1])));
                const float o2 = fmaf(acc[mt][4][hb], x, fmaf(acc[mt][4][hb + 1], y,
                                 fmaf(acc[mt][5][hb], z, acc[mt][5][hb + 1])));
                float* op = out + ((size_t)b * V + v) * 3;
                op[0] = o0; op[1] = o1; op[2] = o2;
            }
        }
    }
}

extern "C" void kernel_launch(void* const* d_in, const int* in_sizes, int n_in,
                              void* d_out, int out_size) {
    const float* verts = (const float*)d_in[0];   // [1,V,3]
    const float* W     = (const float*)d_in[1];   // [1,V,NJ]
    const float* M     = (const float*)d_in[2];   // [NB,NJ,4,4]
    float* out         = (float*)d_out;           // [NB,V,3]

    const int V = in_sizes[0] / 3;

    cudaFuncSetAttribute(skin_mma_kernel,
                         cudaFuncAttributeMaxDynamicSharedMemorySize, S_TOTAL);

    prep_B_kernel<<<NTG, THREADS>>>(M);

    const int grid = (V + MT - 1) / MT;
    skin_mma_kernel<<<grid, THREADS, S_TOTAL>>>(verts, W, out, V);
}

// round 15
// speedup vs baseline: 2.2620x; 1.0114x over previous
#include <cuda_runtime.h>
#include <cuda_fp16.h>
#include <cstdint>

// Problem constants
#define NJ 52
#define NB 32
#define MT 128           // vertices per CTA (GEMM M tile)
#define NTG 48           // n-tiles of 8 (total N = 384 permuted cols)
#define THREADS 256      // 8 warps: 4 (M) x 2 (N)
#define NCHUNK 4         // N chunks of 96 cols

// Main-kernel SMEM (dynamic): A (fp16) + staged B fragments
#define S_A 0
#define S_B (MT * 128)                    // 16384
#define S_TOTAL (S_B + NTG * 4 * 32 * 8)  // 16384 + 49152 = 65536

#define SW128(b) ((b) ^ (((b) >> 3) & 0x70))

// B fragments (fp16): [ntg][kt][lane] -> uint2 {b0,b1}
// Column permutation: within 48-col group g, position p = 8t+2q+d holds
// (batch 4g+q, element e = 2t+d), e = i*4+k over rows 0..2 of the 4x4.
__device__ __align__(16) uint2 g_Bf[NTG * 4 * 32];

__device__ __forceinline__ uint32_t smem_u32(const void* p) {
    uint32_t a;
    asm("{ .reg .u64 t; cvta.to.shared.u64 t, %1; cvt.u32.u64 %0, t; }"
        : "=r"(a) : "l"(p));
    return a;
}

__device__ __forceinline__ void ldsm_x4(uint32_t* d, uint32_t addr) {
    asm volatile("ldmatrix.sync.aligned.m8n8.x4.shared.b16 {%0,%1,%2,%3}, [%4];"
                 : "=r"(d[0]), "=r"(d[1]), "=r"(d[2]), "=r"(d[3]) : "r"(addr));
}

__device__ __forceinline__ void ldsm_x2(uint32_t& d0, uint32_t& d1, uint32_t addr) {
    asm volatile("ldmatrix.sync.aligned.m8n8.x2.shared.b16 {%0,%1}, [%2];"
                 : "=r"(d0), "=r"(d1) : "r"(addr));
}

__device__ __forceinline__ void mma_f16(float* c, const uint32_t* a,
                                        uint32_t b0, uint32_t b1) {
    asm volatile(
        "mma.sync.aligned.m16n8k16.row.col.f32.f16.f16.f32 "
        "{%0,%1,%2,%3}, {%4,%5,%6,%7}, {%8,%9}, {%0,%1,%2,%3};"
        : "+f"(c[0]), "+f"(c[1]), "+f"(c[2]), "+f"(c[3])
        : "r"(a[0]), "r"(a[1]), "r"(a[2]), "r"(a[3]), "r"(b0), "r"(b1));
}

// ---------------- Prep kernel: build permuted B fragments (48 CTAs) ---------
__global__ void __launch_bounds__(THREADS)
prep_B_kernel(const float* __restrict__ M) {
    __shared__ __align__(128) char pb[8 * 128];   // 8 rows x 128B (fp16 K=64)
    const int tid = threadIdx.x;
    const int lane = tid & 31;
    const int ntg = blockIdx.x;

    if (tid < 8 * 32) {                 // one (row, col-pair) per thread
        const int nl = tid >> 5;        // local n row 0..7 = 2q+d
        const int jp = tid & 31;
        const int g = ntg / 6;
        const int t = ntg - g * 6;
        const int b = 4 * g + (nl >> 1);   // batch
        const int e = 2 * t + (nl & 1);    // element 0..11
        const int j0 = 2 * jp, j1 = 2 * jp + 1;
        float m0 = (j0 < NJ) ? M[((size_t)b * NJ + j0) * 16 + e] : 0.0f;
        float m1 = (j1 < NJ) ? M[((size_t)b * NJ + j1) * 16 + e] : 0.0f;
        __half2 hp;
        hp.x = __float2half(m0);
        hp.y = __float2half(m1);
        uint32_t off = SW128((uint32_t)(nl * 128 + jp * 4));
        *reinterpret_cast<__half2*>(pb + off) = hp;
    }
    __syncthreads();

    if (tid < 32) {
        const uint32_t sbp = smem_u32(pb);
        const int bsub = (lane >> 3) & 1;
        const int brin = lane & 7;
        #pragma unroll
        for (int kt = 0; kt < 4; kt++) {
            const uint32_t byte = (uint32_t)(brin * 128 + kt * 32 + bsub * 16);
            const uint32_t sw = SW128(byte);
            uint32_t b0, b1;
            ldsm_x2(b0, b1, sbp + sw);
            g_Bf[(ntg * 4 + kt) * 32 + lane] = make_uint2(b0, b1);
        }
    }
}

// ---------------- Main kernel ----------------------------------------------
__global__ void __launch_bounds__(THREADS, 2)
skin_mma_kernel(const float* __restrict__ verts,   // [V,3]
                const float* __restrict__ W,       // [V,NJ]
                float* __restrict__ out,           // [NB,V,3]
                int V) {
    extern __shared__ char smem[];
    const uint32_t sb = smem_u32(smem);
    const int tid = threadIdx.x;
    const int lane = tid & 31;
    const int wid = tid >> 5;
    const int warp_m = wid >> 1;     // 0..3
    const int warp_n = wid & 1;      // 0..1
    const int vbase = blockIdx.x * MT;

    // ---- Stage B fragments into smem: 3072 coalesced uint4 (48KB) ----
    {
        const uint4* src = reinterpret_cast<const uint4*>(g_Bf);
        uint4* dst = reinterpret_cast<uint4*>(smem + S_B);
        #pragma unroll
        for (int i = 0; i < (NTG * 4 * 32 * 8) / 16 / THREADS; i++)
            dst[tid + i * THREADS] = src[tid + i * THREADS];
    }

    // ---- Zero only the K-pad bytes 104..127 of each A row ----
    {
        const uint2 z = make_uint2(0, 0);
        for (int i = tid; i < MT * 3; i += THREADS) {   // 384 uint2
            const int r = i / 3;
            const int q = i - r * 3;
            const uint32_t off = SW128((uint32_t)(r * 128 + 104 + q * 8));
            *reinterpret_cast<uint2*>(smem + S_A + off) = z;
        }
    }

    // ---- Coalesced A fill: W block contiguous 128*52 floats = 1664 uint4 ----
    {
        const uint4* wp4 = reinterpret_cast<const uint4*>(W + (size_t)vbase * NJ);
        const int lim4 = (V - vbase) * (NJ / 4);   // valid uint4 count in block
        for (int i = tid; i < MT * (NJ / 4); i += THREADS) {
            uint4 raw = (i < lim4) ? wp4[i] : make_uint4(0, 0, 0, 0);
            const int r = i / (NJ / 4);
            const int q = i - r * (NJ / 4);
            const float* f = reinterpret_cast<const float*>(&raw);
            __half2 p0, p1;
            p0.x = __float2half(f[0]); p0.y = __float2half(f[1]);
            p1.x = __float2half(f[2]); p1.y = __float2half(f[3]);
            uint2 packed;
            packed.x = *reinterpret_cast<uint32_t*>(&p0);
            packed.y = *reinterpret_cast<uint32_t*>(&p1);
            const uint32_t off = SW128((uint32_t)(r * 128 + q * 8));  // 8B-aligned
            *reinterpret_cast<uint2*>(smem + S_A + off) = packed;
        }
    }
    __syncthreads();   // the ONLY block-wide sync

    // ---- A fragments persistent: 2 m-tiles x 4 k-tiles ----
    uint32_t ah[2][4][4];
    {
        const int sub = lane >> 3;
        const int rin = lane & 7;
        #pragma unroll
        for (int mt = 0; mt < 2; mt++) {
            const int row = warp_m * 32 + mt * 16 + rin + (sub & 1) * 8;
            const uint32_t byte = (uint32_t)(row * 128 + (sub >> 1) * 16);
            const uint32_t sw = SW128(byte);   // byte bits 5-6 are 0 -> kt via XOR
            const uint32_t base = sb + S_A + sw;
            #pragma unroll
            for (int kt = 0; kt < 4; kt++)
                ldsm_x4(ah[mt][kt], base ^ (uint32_t)(kt * 32));
        }
    }
    const int q = lane & 3;
    const int rg = lane >> 2;

    // ---- N chunks: B via LDS.64 (29cyc, covered), mma, register fold ----
    #pragma unroll 1
    for (int c = 0; c < NCHUNK; c++) {
        // B smem base for this warp's 6 n-tiles at kt=0, this lane
        const uint2* bp = reinterpret_cast<const uint2*>(smem + S_B) +
                          ((size_t)(c * 12 + warp_n * 6) * 4) * 32 + lane;
        float acc[2][6][4] = {};

        #pragma unroll
        for (int kt = 0; kt < 4; kt++) {
            #pragma unroll
            for (int nt = 0; nt < 6; nt++) {
                const uint2 bb = bp[nt * 128 + kt * 32];
                mma_f16(acc[0][nt], ah[0][kt], bb.x, bb.y);
                mma_f16(acc[1][nt], ah[1][kt], bb.x, bb.y);
            }
        }

        // ---- In-register fold + store ----
        const int b = 8 * c + 4 * warp_n + q;
        #pragma unroll
        for (int rr = 0; rr < 4; rr++) {
            const int mt = rr >> 1;
            const int hb = (rr & 1) * 2;
            const int row = warp_m * 32 + mt * 16 + (rr & 1) * 8 + rg;
            const int v = vbase + row;
            if (v < V) {
                const float x = verts[(size_t)v * 3 + 0];
                const float y = verts[(size_t)v * 3 + 1];
                const float z = verts[(size_t)v * 3 + 2];
                const float o0 = fmaf(acc[mt][0][hb], x, fmaf(acc[mt][0][hb + 1], y,
                                 fmaf(acc[mt][1][hb], z, acc[mt][1][hb + 1])));
                const float o1 = fmaf(acc[mt][2][hb], x, fmaf(acc[mt][2][hb + 1], y,
                                 fmaf(acc[mt][3][hb], z, acc[mt][3][hb + 1])));
                const float o2 = fmaf(acc[mt][4][hb], x, fmaf(acc[mt][4][hb + 1], y,
                                 fmaf(acc[mt][5][hb], z, acc[mt][5][hb + 1])));
                float* op = out + ((size_t)b * V + v) * 3;
                op[0] = o0; op[1] = o1; op[2] = o2;
            }
        }
    }
}

extern "C" void kernel_launch(void* const* d_in, const int* in_sizes, int n_in,
                              void* d_out, int out_size) {
    const float* verts = (const float*)d_in[0];   // [1,V,3]
    const float* W     = (const float*)d_in[1];   // [1,V,NJ]
    const float* M     = (const float*)d_in[2];   // [NB,NJ,4,4]
    float* out         = (float*)d_out;           // [NB,V,3]

    const int V = in_sizes[0] / 3;

    cudaFuncSetAttribute(skin_mma_kernel,
                         cudaFuncAttributeMaxDynamicSharedMemorySize, S_TOTAL);

    prep_B_kernel<<<NTG, THREADS>>>(M);

    const int grid = (V + MT - 1) / MT;
    skin_mma_kernel<<<grid, THREADS, S_TOTAL>>>(verts, W, out, V);
}